// round 2
// baseline (speedup 1.0000x reference)
#include <cuda_runtime.h>

// IntentGCN fused kernel: one block per (n,t) slice.
// N=32, C_IN=C_OUT=64, K=3, T=300, V=25, H=4, DK=DV=16.

#define VN 25
#define VP 28   // padded token count (for float4 tiles)

// shared memory float offsets
#define OF_FAT  0        // faT[64][28]  (bn1 output, transposed, padded cols zeroed)
#define OF_QNT  1792     // qnT[64][28]  (LayerNorm output, transposed)
#define OF_Q    3584     // q[25][65]    (also base of g[75][64] overlay, 4800 <= 4896)
#define OF_K    5216     // k[25][65]
#define OF_V    6848     // v[25][65]
#define OF_SC   8480     // scores [4][25][25] = 2500 (padded region 2512)
#define OF_XOT  10992    // xoT[64][28]
#define OF_FA2  12784    // f_a[25][65]
#define OF_A    14416    // A padded [75][28] (w cols 25..27 zeroed)
#define OF_W    16528    // staged weight matrix, 4096 floats
#define OF_MISC 20624    // bn1 s/b (128), bn2 s/b (128), mu(32), rstd(32), gate
#define SMEM_FLOATS 20960
#define SMEM_BYTES (SMEM_FLOATS * 4)

__global__ __launch_bounds__(512, 2)
void intentgcn_kernel(
    const float* __restrict__ x,    const float* __restrict__ Ag,
    const float* __restrict__ bn1g, const float* __restrict__ bn1b,
    const float* __restrict__ bn1m, const float* __restrict__ bn1v,
    const float* __restrict__ convw, const float* __restrict__ convb,
    const float* __restrict__ lng,  const float* __restrict__ lnb,
    const float* __restrict__ wq,   const float* __restrict__ wk,
    const float* __restrict__ wv,   const float* __restrict__ fcw,
    const float* __restrict__ gatep,
    const float* __restrict__ bn2g, const float* __restrict__ bn2b,
    const float* __restrict__ bn2m, const float* __restrict__ bn2v,
    float* __restrict__ out)
{
    extern __shared__ float sm[];
    float* sFAT = sm + OF_FAT;
    float* sQNT = sm + OF_QNT;
    float* sQ   = sm + OF_Q;
    float* sK   = sm + OF_K;
    float* sV   = sm + OF_V;
    float* sG   = sm + OF_Q;     // overlay: g[(k*25+v)*64 + co], q/k/v dead by then
    float* sSC  = sm + OF_SC;
    float* sXOT = sm + OF_XOT;
    float* sFA2 = sm + OF_FA2;
    float* sA   = sm + OF_A;
    float* sW   = sm + OF_W;
    float* sB1S = sm + OF_MISC;
    float* sB1B = sB1S + 64;
    float* sB2S = sB1B + 64;
    float* sB2B = sB2S + 64;
    float* sMU  = sB2B + 64;     // 25 used (32 reserved)
    float* sRS  = sMU + 32;      // 25 used (32 reserved)
    float* sGate = sRS + 32;

    const int tid = threadIdx.x;
    const int t = blockIdx.x;
    const int n = blockIdx.y;

    // ---------------- P0: params, A load, pad-zeroing ----------------
    if (tid < 64) {
        float s1 = bn1g[tid] * rsqrtf(bn1v[tid] + 1e-5f);
        sB1S[tid] = s1;
        sB1B[tid] = bn1b[tid] - bn1m[tid] * s1;
        float s2 = bn2g[tid] * rsqrtf(bn2v[tid] + 1e-5f);
        sB2S[tid] = s2;
        sB2B[tid] = bn2b[tid] - bn2m[tid] * s2;
    }
    if (tid == 0) sGate[0] = gatep[0];
    for (int i = tid; i < 192; i += 512) {           // zero padded v-cols
        int c = i / 3, vp = VN + i % 3;
        sFAT[c*VP + vp] = 0.f;
        sQNT[c*VP + vp] = 0.f;
        sXOT[c*VP + vp] = 0.f;
    }
    for (int i = tid; i < 225; i += 512)             // zero padded A w-cols
        sA[(i/3)*VP + VN + i % 3] = 0.f;
    for (int i = tid; i < 1875; i += 512) {          // A[3*25][25] -> padded rows
        int kv = i / 25, w = i - kv*25;
        sA[kv*VP + w] = Ag[i];
    }
    __syncthreads();

    // ---------------- P0b: fa = bn1(x), stored transposed faT[c][v] ----------------
    const float* xb = x + (size_t)(n*64*300 + t) * 25;   // + c*300*25 + v
    for (int i = tid; i < 1600; i += 512) {
        int c = i / 25, v = i - c*25;
        float xv = xb[c*7500 + v];
        sFAT[c*VP + v] = xv * sB1S[c] + sB1B[c];
    }
    __syncthreads();

    // ---------------- P0c: per-token LayerNorm stats ----------------
    if (tid < VN) {
        float s = 0.f;
        #pragma unroll
        for (int c = 0; c < 64; c++) s += sFAT[c*VP + tid];
        float mu = s * (1.f/64.f);
        float s2 = 0.f;
        #pragma unroll
        for (int c = 0; c < 64; c++) { float d = sFAT[c*VP + tid] - mu; s2 += d*d; }
        sMU[tid] = mu;
        sRS[tid] = rsqrtf(s2 * (1.f/64.f) + 1e-6f);
    }
    __syncthreads();

    // ---------------- P0d: qn (transposed) ----------------
    for (int i = tid; i < 1600; i += 512) {
        int c = i / 25, v = i - c*25;
        sQNT[c*VP + v] = (sFAT[c*VP + v] - sMU[v]) * sRS[v] * lng[c] + lnb[c];
    }
    __syncthreads();

    // ---------------- P1: q/k/v GEMMs (staged weights, 4-v register tiles) ----------------
    for (int m = 0; m < 3; m++) {
        const float* wsrc = (m == 0) ? wq : ((m == 1) ? wk : wv);
        for (int i = tid; i < 4096; i += 512) sW[i] = wsrc[i];
        __syncthreads();
        const float* src = (m == 0) ? sQNT : sFAT;
        float* dst = (m == 0) ? sQ : ((m == 1) ? sK : sV);
        if (tid < 448) {
            int d = tid / 7, vg = tid % 7;
            const float4* s4 = reinterpret_cast<const float4*>(src) + vg;
            float a0 = 0.f, a1 = 0.f, a2 = 0.f, a3 = 0.f;
            #pragma unroll 8
            for (int c = 0; c < 64; c++) {
                float4 sv4 = s4[c*7];
                float w = sW[c*64 + d];
                a0 += sv4.x*w; a1 += sv4.y*w; a2 += sv4.z*w; a3 += sv4.w*w;
            }
            int v0 = vg * 4;
            dst[v0*65 + d] = a0;
            if (v0 + 3 < VN) {
                dst[(v0+1)*65 + d] = a1;
                dst[(v0+2)*65 + d] = a2;
                dst[(v0+3)*65 + d] = a3;
            }
        }
        __syncthreads();
    }

    // stage fc_w while computing scores (consumed at P5; barriers in between)
    for (int i = tid; i < 4096; i += 512) sW[i] = fcw[i];

    // ---------------- P2: scores[h][vq][w] = q.k / 4 ----------------
    for (int i = tid; i < 2500; i += 512) {
        int h = i / 625, r = i - h*625;
        int vq = r / 25, w = r - vq*25;
        const float* qp = sQ + vq*65 + h*16;
        const float* kp = sK + w*65 + h*16;
        float acc = 0.f;
        #pragma unroll
        for (int d = 0; d < 16; d++) acc += qp[d] * kp[d];
        sSC[i] = acc * 0.25f;
    }
    __syncthreads();

    // ---------------- P3: softmax over w (100 rows) ----------------
    if (tid < 100) {
        float* row = sSC + tid*25;
        float mx = row[0];
        #pragma unroll
        for (int j = 1; j < 25; j++) mx = fmaxf(mx, row[j]);
        float s = 0.f;
        #pragma unroll
        for (int j = 0; j < 25; j++) { float e = __expf(row[j] - mx); row[j] = e; s += e; }
        float inv = 1.f / s;
        #pragma unroll
        for (int j = 0; j < 25; j++) row[j] *= inv;
    }
    __syncthreads();

    // ---------------- P4: xo = attn @ v  (stored transposed xoT[e][v]) ----------------
    for (int i = tid; i < 1600; i += 512) {
        int e = i / 25, v = i - e*25;
        int h = e >> 4;
        const float* ap = sSC + h*625 + v*25;
        float acc = 0.f;
        #pragma unroll
        for (int w = 0; w < 25; w++) acc += ap[w] * sV[w*65 + e];
        sXOT[e*VP + v] = acc;
    }
    __syncthreads();

    // ---------------- P5: f_a = xo @ fc_w + residual(fa) ----------------
    if (tid < 448) {
        int c = tid / 7, vg = tid % 7;
        int v0 = vg * 4;
        float a0 = sFAT[c*VP + v0 + 0];   // residual (padded cols are zero)
        float a1 = sFAT[c*VP + v0 + 1];
        float a2 = sFAT[c*VP + v0 + 2];
        float a3 = sFAT[c*VP + v0 + 3];
        const float4* x4 = reinterpret_cast<const float4*>(sXOT) + vg;
        #pragma unroll 8
        for (int e = 0; e < 64; e++) {
            float4 xv = x4[e*7];
            float w = sW[e*64 + c];
            a0 += xv.x*w; a1 += xv.y*w; a2 += xv.z*w; a3 += xv.w*w;
        }
        sFA2[v0*65 + c] = a0;
        if (v0 + 3 < VN) {
            sFA2[(v0+1)*65 + c] = a1;
            sFA2[(v0+2)*65 + c] = a2;
            sFA2[(v0+3)*65 + c] = a3;
        }
    }
    __syncthreads();

    // ---------------- P6: conv branch g[k][v][co] = fa @ conv_w^T + bias ----------------
    for (int k = 0; k < 3; k++) {
        for (int i = tid; i < 4096; i += 512) sW[i] = convw[k*4096 + i];
        __syncthreads();
        if (tid < 448) {
            int co = tid / 7, vg = tid % 7;
            float bias = convb[k*64 + co];
            float a0 = bias, a1 = bias, a2 = bias, a3 = bias;
            const float4* f4 = reinterpret_cast<const float4*>(sFAT) + vg;
            #pragma unroll 8
            for (int ci = 0; ci < 64; ci++) {
                float4 fv = f4[ci*7];
                float w = sW[co*64 + ci];
                a0 += fv.x*w; a1 += fv.y*w; a2 += fv.z*w; a3 += fv.w*w;
            }
            int v0 = vg * 4;
            sG[(k*25 + v0)*64 + co] = a0;
            if (v0 + 3 < VN) {
                sG[(k*25 + v0 + 1)*64 + co] = a1;
                sG[(k*25 + v0 + 2)*64 + co] = a2;
                sG[(k*25 + v0 + 3)*64 + co] = a3;
            }
        }
        __syncthreads();
    }

    // ---------------- P7: f_c = g x A, combine, bn2, relu, store ----------------
    float gate = sGate[0];
    if (tid < 448) {
        int co = tid / 7, wg = tid % 7;
        float a0 = 0.f, a1 = 0.f, a2 = 0.f, a3 = 0.f;
        const float4* a4 = reinterpret_cast<const float4*>(sA) + wg;
        #pragma unroll 5
        for (int kv = 0; kv < 75; kv++) {
            float gv = sG[kv*64 + co];
            float4 av = a4[kv*7];
            a0 += gv*av.x; a1 += gv*av.y; a2 += gv*av.z; a3 += gv*av.w;
        }
        float s2 = sB2S[co], b2 = sB2B[co];
        float* ob = out + ((size_t)(n*64 + co)*300 + t) * 25;
        float acc[4] = {a0, a1, a2, a3};
        int w0 = wg * 4;
        #pragma unroll
        for (int j = 0; j < 4; j++) {
            int w = w0 + j;
            if (w < VN) {
                float f = (sFA2[w*65 + co] * gate + acc[j]) * 0.5f;
                float val = f * s2 + b2;
                ob[w] = fmaxf(val, 0.f);
            }
        }
    }
}

extern "C" void kernel_launch(void* const* d_in, const int* in_sizes, int n_in,
                              void* d_out, int out_size) {
    const float* x     = (const float*)d_in[0];
    const float* Ag    = (const float*)d_in[1];
    const float* bn1g  = (const float*)d_in[2];
    const float* bn1b  = (const float*)d_in[3];
    const float* bn1m  = (const float*)d_in[4];
    const float* bn1v  = (const float*)d_in[5];
    const float* convw = (const float*)d_in[6];
    const float* convb = (const float*)d_in[7];
    const float* lng   = (const float*)d_in[8];
    const float* lnb   = (const float*)d_in[9];
    const float* wq    = (const float*)d_in[10];
    const float* wk    = (const float*)d_in[11];
    const float* wv    = (const float*)d_in[12];
    const float* fcw   = (const float*)d_in[13];
    const float* gatep = (const float*)d_in[14];
    const float* bn2g  = (const float*)d_in[15];
    const float* bn2b  = (const float*)d_in[16];
    const float* bn2m  = (const float*)d_in[17];
    const float* bn2v  = (const float*)d_in[18];
    float* outp = (float*)d_out;

    (void)cudaFuncSetAttribute(intentgcn_kernel,
                               cudaFuncAttributeMaxDynamicSharedMemorySize, SMEM_BYTES);
    dim3 grid(300, 32);
    intentgcn_kernel<<<grid, 512, SMEM_BYTES>>>(
        x, Ag, bn1g, bn1b, bn1m, bn1v, convw, convb, lng, lnb,
        wq, wk, wv, fcw, gatep, bn2g, bn2b, bn2m, bn2v, outp);
}

// round 4
// speedup vs baseline: 1.7825x; 1.7825x over previous
#include <cuda_runtime.h>

// IntentGCN fused kernel v2: one block per (n,t) slice, 4x4 register tiles,
// weights streamed via LDG (L1-resident), activations via LDS.
// N=32, C_IN=C_OUT=64, K=3, T=300, V=25, H=4, DK=DV=16.

#define VP 28    // padded v (stride for [*][v] arrays)
#define VB_S 68  // stride for [v][64] arrays (float4-aligned, odd/4 for banks)

// shared memory float offsets
#define OF_FAT  0        // faT[64][28]   bn1 output, transposed
#define OF_QNT  1792     // qnT[64][28]   LayerNorm output, transposed
#define OF_QT   3584     // qT[64][28]    (rows = h*16+d)
#define OF_KT   5376     // kT[64][28]
#define OF_VB   7168     // vB[25][68]    v[w][e]
#define OF_SC   8868     // scT[4][28][28]  (scores stored [h][w][vq])
#define OF_XOT  12004    // xoT[64][28]
#define OF_FA2  13796    // fa2[25][68]   f_a[v][c]
#define OF_G    15496    // g[75][64]
#define OF_A    20296    // A[75][28]
#define OF_MISC 22396
#define SMEM_FLOATS 22852
#define SMEM_BYTES (SMEM_FLOATS * 4)

__global__ __launch_bounds__(512, 2)
void intentgcn_kernel(
    const float* __restrict__ x,    const float* __restrict__ Ag,
    const float* __restrict__ bn1g, const float* __restrict__ bn1b,
    const float* __restrict__ bn1m, const float* __restrict__ bn1v,
    const float* __restrict__ convw, const float* __restrict__ convb,
    const float* __restrict__ lng,  const float* __restrict__ lnb,
    const float* __restrict__ wq,   const float* __restrict__ wk,
    const float* __restrict__ wv,   const float* __restrict__ fcw,
    const float* __restrict__ gatep,
    const float* __restrict__ bn2g, const float* __restrict__ bn2b,
    const float* __restrict__ bn2m, const float* __restrict__ bn2v,
    float* __restrict__ out)
{
    extern __shared__ float sm[];
    float* sFAT = sm + OF_FAT;
    float* sQNT = sm + OF_QNT;
    float* sQT  = sm + OF_QT;
    float* sKT  = sm + OF_KT;
    float* sVB  = sm + OF_VB;
    float* sSC  = sm + OF_SC;
    float* sXOT = sm + OF_XOT;
    float* sFA2 = sm + OF_FA2;
    float* sG   = sm + OF_G;
    float* sA   = sm + OF_A;
    float* sB1S = sm + OF_MISC;
    float* sB1B = sB1S + 64;
    float* sB2S = sB1B + 64;
    float* sB2B = sB2S + 64;
    float* sLNg = sB2B + 64;
    float* sLNb = sLNg + 64;
    float* sMU  = sLNb + 64;   // 32
    float* sRS  = sMU + 32;    // 32
    float* sGate = sRS + 32;

    const int tid = threadIdx.x;
    const int t = blockIdx.x;
    const int n = blockIdx.y;

    // ---------------- P0a: params, A, pad-zeroing ----------------
    if (tid < 64) {
        float s1 = bn1g[tid] * rsqrtf(bn1v[tid] + 1e-5f);
        sB1S[tid] = s1;
        sB1B[tid] = bn1b[tid] - bn1m[tid] * s1;
        float s2 = bn2g[tid] * rsqrtf(bn2v[tid] + 1e-5f);
        sB2S[tid] = s2;
        sB2B[tid] = bn2b[tid] - bn2m[tid] * s2;
        sLNg[tid] = lng[tid];
        sLNb[tid] = lnb[tid];
    }
    if (tid == 0) sGate[0] = gatep[0];
    for (int i = tid; i < 192; i += 512) {           // zero padded v-cols
        int c = i / 3, vp = 25 + i % 3;
        sFAT[c*VP + vp] = 0.f;
        sQNT[c*VP + vp] = 0.f;
    }
    for (int i = tid; i < 225; i += 512)             // zero padded A w-cols
        sA[(i/3)*VP + 25 + i % 3] = 0.f;
    for (int i = tid; i < 1875; i += 512) {          // A[75][25] -> stride 28
        int kv = i / 25, w = i - kv*25;
        sA[kv*VP + w] = Ag[i];
    }
    __syncthreads();

    // ---------------- P0b: fa = bn1(x), stored faT[c][v] ----------------
    const float* xb = x + (size_t)(n*64*300 + t) * 25;
    for (int i = tid; i < 1600; i += 512) {
        int c = i / 25, v = i - c*25;
        sFAT[c*VP + v] = xb[c*7500 + v] * sB1S[c] + sB1B[c];
    }
    __syncthreads();

    // ---------------- P0c: per-token LayerNorm stats ----------------
    if (tid < 25) {
        float s = 0.f;
        #pragma unroll
        for (int c = 0; c < 64; c++) s += sFAT[c*VP + tid];
        float mu = s * (1.f/64.f);
        float s2 = 0.f;
        #pragma unroll
        for (int c = 0; c < 64; c++) { float d = sFAT[c*VP + tid] - mu; s2 += d*d; }
        sMU[tid] = mu;
        sRS[tid] = rsqrtf(s2 * (1.f/64.f) + 1e-6f);
    }
    __syncthreads();

    // ---------------- P0d: qn (transposed) ----------------
    for (int i = tid; i < 1600; i += 512) {
        int c = i / 25, v = i - c*25;
        sQNT[c*VP + v] = (sFAT[c*VP + v] - sMU[v]) * sRS[v] * sLNg[c] + sLNb[c];
    }
    __syncthreads();

    // ---------------- P1: q/k/v projections (4x4 tiles, weights via LDG) ----
    if (tid < 336) {
        int m = tid / 112, r = tid % 112;
        int vg = r % 7, dg = r / 7;          // dg 0..15
        int v0 = vg * 4, d0 = dg * 4;
        const float* src = (m == 0) ? sQNT : sFAT;
        const float* wsel = (m == 0) ? wq : ((m == 1) ? wk : wv);
        float acc[4][4];
        #pragma unroll
        for (int i = 0; i < 4; i++)
            #pragma unroll
            for (int j = 0; j < 4; j++) acc[i][j] = 0.f;
        #pragma unroll 4
        for (int c = 0; c < 64; c++) {
            float4 a4 = *reinterpret_cast<const float4*>(src + c*VP + v0);
            float4 b4 = *reinterpret_cast<const float4*>(wsel + c*64 + d0);
            acc[0][0] += b4.x*a4.x; acc[0][1] += b4.x*a4.y; acc[0][2] += b4.x*a4.z; acc[0][3] += b4.x*a4.w;
            acc[1][0] += b4.y*a4.x; acc[1][1] += b4.y*a4.y; acc[1][2] += b4.y*a4.z; acc[1][3] += b4.y*a4.w;
            acc[2][0] += b4.z*a4.x; acc[2][1] += b4.z*a4.y; acc[2][2] += b4.z*a4.z; acc[2][3] += b4.z*a4.w;
            acc[3][0] += b4.w*a4.x; acc[3][1] += b4.w*a4.y; acc[3][2] += b4.w*a4.z; acc[3][3] += b4.w*a4.w;
        }
        if (m < 2) {
            float* dst = (m == 0) ? sQT : sKT;
            #pragma unroll
            for (int di = 0; di < 4; di++) {
                float4 o; o.x = acc[di][0]; o.y = acc[di][1]; o.z = acc[di][2]; o.w = acc[di][3];
                *reinterpret_cast<float4*>(dst + (d0+di)*VP + v0) = o;
            }
        } else {
            #pragma unroll
            for (int vi = 0; vi < 4; vi++) {
                if (v0 + vi < 25) {
                    #pragma unroll
                    for (int di = 0; di < 4; di++)
                        sVB[(v0+vi)*VB_S + d0 + di] = acc[di][vi];
                }
            }
        }
    }
    __syncthreads();

    // ---------------- P2: scores scT[h][w][vq] = (q.k)/4 ----------------
    if (tid < 196) {
        int h = tid / 49, rr = tid % 49;
        int wg = rr % 7, vqg = rr / 7;
        int w0 = wg * 4, vq0 = vqg * 4;
        const float* qb = sQT + h*16*VP;
        const float* kb = sKT + h*16*VP;
        float acc[4][4];
        #pragma unroll
        for (int i = 0; i < 4; i++)
            #pragma unroll
            for (int j = 0; j < 4; j++) acc[i][j] = 0.f;
        #pragma unroll 4
        for (int d = 0; d < 16; d++) {
            float4 a4 = *reinterpret_cast<const float4*>(qb + d*VP + vq0);
            float4 b4 = *reinterpret_cast<const float4*>(kb + d*VP + w0);
            acc[0][0] += b4.x*a4.x; acc[0][1] += b4.x*a4.y; acc[0][2] += b4.x*a4.z; acc[0][3] += b4.x*a4.w;
            acc[1][0] += b4.y*a4.x; acc[1][1] += b4.y*a4.y; acc[1][2] += b4.y*a4.z; acc[1][3] += b4.y*a4.w;
            acc[2][0] += b4.z*a4.x; acc[2][1] += b4.z*a4.y; acc[2][2] += b4.z*a4.z; acc[2][3] += b4.z*a4.w;
            acc[3][0] += b4.w*a4.x; acc[3][1] += b4.w*a4.y; acc[3][2] += b4.w*a4.z; acc[3][3] += b4.w*a4.w;
        }
        float* scb = sSC + h*784;
        #pragma unroll
        for (int wi = 0; wi < 4; wi++) {
            float4 o; o.x = acc[wi][0]*0.25f; o.y = acc[wi][1]*0.25f;
            o.z = acc[wi][2]*0.25f; o.w = acc[wi][3]*0.25f;
            *reinterpret_cast<float4*>(scb + (w0+wi)*VP + vq0) = o;
        }
    }
    __syncthreads();

    // ---------------- P3: softmax over w (column-wise in scT) ----------------
    if (tid < 100) {
        int h = tid / 25, vq = tid % 25;
        float* col = sSC + h*784 + vq;
        float mx = col[0];
        #pragma unroll
        for (int w = 1; w < 25; w++) mx = fmaxf(mx, col[w*VP]);
        float s = 0.f;
        #pragma unroll
        for (int w = 0; w < 25; w++) { float e = __expf(col[w*VP] - mx); col[w*VP] = e; s += e; }
        float inv = 1.f / s;
        #pragma unroll
        for (int w = 0; w < 25; w++) col[w*VP] *= inv;
    }
    __syncthreads();

    // ---------------- P4: xoT[e][v] = sum_w attn[h][w][v] * vB[w][e] ----------
    if (tid < 112) {
        int vg = tid % 7, eg = tid / 7;      // eg 0..15
        int v0 = vg * 4, e0 = eg * 4;
        int h = eg >> 2;
        const float* scb = sSC + h*784;
        float acc[4][4];
        #pragma unroll
        for (int i = 0; i < 4; i++)
            #pragma unroll
            for (int j = 0; j < 4; j++) acc[i][j] = 0.f;
        #pragma unroll 5
        for (int w = 0; w < 25; w++) {
            float4 a4 = *reinterpret_cast<const float4*>(sVB + w*VB_S + e0);
            float4 b4 = *reinterpret_cast<const float4*>(scb + w*VP + v0);
            acc[0][0] += a4.x*b4.x; acc[0][1] += a4.x*b4.y; acc[0][2] += a4.x*b4.z; acc[0][3] += a4.x*b4.w;
            acc[1][0] += a4.y*b4.x; acc[1][1] += a4.y*b4.y; acc[1][2] += a4.y*b4.z; acc[1][3] += a4.y*b4.w;
            acc[2][0] += a4.z*b4.x; acc[2][1] += a4.z*b4.y; acc[2][2] += a4.z*b4.z; acc[2][3] += a4.z*b4.w;
            acc[3][0] += a4.w*b4.x; acc[3][1] += a4.w*b4.y; acc[3][2] += a4.w*b4.z; acc[3][3] += a4.w*b4.w;
        }
        #pragma unroll
        for (int ei = 0; ei < 4; ei++) {
            float4 o; o.x = acc[ei][0]; o.y = acc[ei][1]; o.z = acc[ei][2]; o.w = acc[ei][3];
            *reinterpret_cast<float4*>(sXOT + (e0+ei)*VP + v0) = o;
        }
    }
    __syncthreads();

    // ---------------- P5||P6 merged ----------------
    if (tid < 112) {
        // P5: fa2[v][c] = xo @ fc_w + residual
        int vg = tid % 7, cg = tid / 7;
        int v0 = vg * 4, c0 = cg * 4;
        float acc[4][4];
        #pragma unroll
        for (int vi = 0; vi < 4; vi++)
            #pragma unroll
            for (int ci = 0; ci < 4; ci++)
                acc[vi][ci] = sFAT[(c0+ci)*VP + v0 + vi];   // residual (0 in pad cols)
        #pragma unroll 4
        for (int e = 0; e < 64; e++) {
            float4 a4 = *reinterpret_cast<const float4*>(sXOT + e*VP + v0);
            float4 b4 = *reinterpret_cast<const float4*>(fcw + e*64 + c0);
            acc[0][0] += a4.x*b4.x; acc[0][1] += a4.x*b4.y; acc[0][2] += a4.x*b4.z; acc[0][3] += a4.x*b4.w;
            acc[1][0] += a4.y*b4.x; acc[1][1] += a4.y*b4.y; acc[1][2] += a4.y*b4.z; acc[1][3] += a4.y*b4.w;
            acc[2][0] += a4.z*b4.x; acc[2][1] += a4.z*b4.y; acc[2][2] += a4.z*b4.z; acc[2][3] += a4.z*b4.w;
            acc[3][0] += a4.w*b4.x; acc[3][1] += a4.w*b4.y; acc[3][2] += a4.w*b4.z; acc[3][3] += a4.w*b4.w;
        }
        #pragma unroll
        for (int vi = 0; vi < 4; vi++) {
            if (v0 + vi < 25) {
                float4 o; o.x = acc[vi][0]; o.y = acc[vi][1]; o.z = acc[vi][2]; o.w = acc[vi][3];
                *reinterpret_cast<float4*>(sFA2 + (v0+vi)*VB_S + c0) = o;
            }
        }
    } else if (tid < 448) {
        // P6: g[k][v][co] = fa @ conv_w[k]^T + bias  (conv_w rows read along ci)
        int r = tid - 112;
        int k = r / 112; r %= 112;
        int vg = r % 7, cog = r / 7;
        int v0 = vg * 4, co0 = cog * 4;
        const float* wb = convw + (k*64 + co0) * 64;
        float acc[4][4];
        #pragma unroll
        for (int coi = 0; coi < 4; coi++) {
            float bv = convb[k*64 + co0 + coi];
            #pragma unroll
            for (int vi = 0; vi < 4; vi++) acc[vi][coi] = bv;
        }
        #pragma unroll 2
        for (int ci0 = 0; ci0 < 64; ci0 += 4) {
            float4 rb0 = *reinterpret_cast<const float4*>(wb + 0*64 + ci0);
            float4 rb1 = *reinterpret_cast<const float4*>(wb + 1*64 + ci0);
            float4 rb2 = *reinterpret_cast<const float4*>(wb + 2*64 + ci0);
            float4 rb3 = *reinterpret_cast<const float4*>(wb + 3*64 + ci0);
            #pragma unroll
            for (int j = 0; j < 4; j++) {
                float4 la = *reinterpret_cast<const float4*>(sFAT + (ci0+j)*VP + v0);
                float w0v = (j==0)?rb0.x:((j==1)?rb0.y:((j==2)?rb0.z:rb0.w));
                float w1v = (j==0)?rb1.x:((j==1)?rb1.y:((j==2)?rb1.z:rb1.w));
                float w2v = (j==0)?rb2.x:((j==1)?rb2.y:((j==2)?rb2.z:rb2.w));
                float w3v = (j==0)?rb3.x:((j==1)?rb3.y:((j==2)?rb3.z:rb3.w));
                acc[0][0] += la.x*w0v; acc[0][1] += la.x*w1v; acc[0][2] += la.x*w2v; acc[0][3] += la.x*w3v;
                acc[1][0] += la.y*w0v; acc[1][1] += la.y*w1v; acc[1][2] += la.y*w2v; acc[1][3] += la.y*w3v;
                acc[2][0] += la.z*w0v; acc[2][1] += la.z*w1v; acc[2][2] += la.z*w2v; acc[2][3] += la.z*w3v;
                acc[3][0] += la.w*w0v; acc[3][1] += la.w*w1v; acc[3][2] += la.w*w2v; acc[3][3] += la.w*w3v;
            }
        }
        #pragma unroll
        for (int vi = 0; vi < 4; vi++) {
            if (v0 + vi < 25) {
                float4 o; o.x = acc[vi][0]; o.y = acc[vi][1]; o.z = acc[vi][2]; o.w = acc[vi][3];
                *reinterpret_cast<float4*>(sG + (k*25 + v0 + vi)*64 + co0) = o;
            }
        }
    }
    __syncthreads();

    // ---------------- P7: f_c = g x A, combine, bn2, relu, store ----------------
    if (tid < 112) {
        int wg = tid % 7, cog = tid / 7;     // cog 0..15
        int w0 = wg * 4, co0 = cog * 4;
        float gate = sGate[0];
        float acc[4][4];
        #pragma unroll
        for (int i = 0; i < 4; i++)
            #pragma unroll
            for (int j = 0; j < 4; j++) acc[i][j] = 0.f;
        #pragma unroll 5
        for (int kv = 0; kv < 75; kv++) {
            float4 a4 = *reinterpret_cast<const float4*>(sA + kv*VP + w0);
            float4 b4 = *reinterpret_cast<const float4*>(sG + kv*64 + co0);
            acc[0][0] += a4.x*b4.x; acc[0][1] += a4.x*b4.y; acc[0][2] += a4.x*b4.z; acc[0][3] += a4.x*b4.w;
            acc[1][0] += a4.y*b4.x; acc[1][1] += a4.y*b4.y; acc[1][2] += a4.y*b4.z; acc[1][3] += a4.y*b4.w;
            acc[2][0] += a4.z*b4.x; acc[2][1] += a4.z*b4.y; acc[2][2] += a4.z*b4.z; acc[2][3] += a4.z*b4.w;
            acc[3][0] += a4.w*b4.x; acc[3][1] += a4.w*b4.y; acc[3][2] += a4.w*b4.z; acc[3][3] += a4.w*b4.w;
        }
        #pragma unroll
        for (int coi = 0; coi < 4; coi++) {
            int co = co0 + coi;
            float s2 = sB2S[co], b2 = sB2B[co];
            float* ob = out + ((size_t)(n*64 + co))*7500 + t*25;
            #pragma unroll
            for (int wi = 0; wi < 4; wi++) {
                int w = w0 + wi;
                if (w < 25) {
                    float f = (sFA2[w*VB_S + co] * gate + acc[wi][coi]) * 0.5f;
                    ob[w] = fmaxf(f * s2 + b2, 0.f);
                }
            }
        }
    }
}

extern "C" void kernel_launch(void* const* d_in, const int* in_sizes, int n_in,
                              void* d_out, int out_size) {
    const float* x     = (const float*)d_in[0];
    const float* Ag    = (const float*)d_in[1];
    const float* bn1g  = (const float*)d_in[2];
    const float* bn1b  = (const float*)d_in[3];
    const float* bn1m  = (const float*)d_in[4];
    const float* bn1v  = (const float*)d_in[5];
    const float* convw = (const float*)d_in[6];
    const float* convb = (const float*)d_in[7];
    const float* lng   = (const float*)d_in[8];
    const float* lnb   = (const float*)d_in[9];
    const float* wq    = (const float*)d_in[10];
    const float* wk    = (const float*)d_in[11];
    const float* wv    = (const float*)d_in[12];
    const float* fcw   = (const float*)d_in[13];
    const float* gatep = (const float*)d_in[14];
    const float* bn2g  = (const float*)d_in[15];
    const float* bn2b  = (const float*)d_in[16];
    const float* bn2m  = (const float*)d_in[17];
    const float* bn2v  = (const float*)d_in[18];
    float* outp = (float*)d_out;

    (void)cudaFuncSetAttribute(intentgcn_kernel,
                               cudaFuncAttributeMaxDynamicSharedMemorySize, SMEM_BYTES);
    dim3 grid(300, 32);
    intentgcn_kernel<<<grid, 512, SMEM_BYTES>>>(
        x, Ag, bn1g, bn1b, bn1m, bn1v, convw, convb, lng, lnb,
        wq, wk, wv, fcw, gatep, bn2g, bn2b, bn2m, bn2v, outp);
}